// round 16
// baseline (speedup 1.0000x reference)
#include <cuda_runtime.h>
#include <cuda_fp16.h>
#include <math.h>

#define NN 100000
#define EE 1600000

typedef unsigned long long u64t;

#define F2PACK(d, lo, hi) asm("mov.b64 %0, {%1, %2};" : "=l"(d) : "f"(lo), "f"(hi))
#define F2UNPACK(lo, hi, v) asm("mov.b64 {%0, %1}, %2;" : "=f"(lo), "=f"(hi) : "l"(v))
#define F2FMA(d, a, b, c) asm("fma.rn.f32x2 %0, %1, %2, %3;" : "=l"(d) : "l"(a), "l"(b), "l"(c))
#define F2MUL(d, a, b) asm("mul.rn.f32x2 %0, %1, %2;" : "=l"(d) : "l"(a), "l"(b))
#define F2ADD(d, a, b) asm("add.rn.f32x2 %0, %1, %2;" : "=l"(d) : "l"(a), "l"(b))

// ---------------- scratch ----------------
__device__ __align__(16) __half g_xw1h[NN * 64];
__device__ __align__(16) float g_xt[NN * 6];       // encoder output
__device__ __align__(16) float g_xw2p[NN * 80];    // partial xw2 (h1-part, fp32)
__device__ __align__(16) __half g_xw2h[NN * 80];
__device__ float g_s1dst[NN * 8];
__device__ float g_s2dst[NN * 8];
__device__ __align__(8) float2 g_s1pack[NN * 8];   // (s_src, exp(0.2 s_src))
__device__ __align__(8) float2 g_s2pack[NN * 8];
__device__ int g_deg[NN];
__device__ int g_rowptr[NN + 1];
__device__ int g_pos[NN];
__device__ int g_col[EE];
__device__ int g_bsum[128];

// ---------------- CSR build ----------------
__global__ void zero_deg_k() {
    int i = blockIdx.x * blockDim.x + threadIdx.x;
    if (i < NN) g_deg[i] = 0;
}

__global__ void hist_k(const int* __restrict__ ei, int E) {
    int e = blockIdx.x * blockDim.x + threadIdx.x;
    if (e >= E) return;
    int s = ei[e], d = ei[E + e];
    if (s != d) atomicAdd(&g_deg[d], 1);
}

__global__ void scan1_k() {
    int b = blockIdx.x, t = threadIdx.x;
    int base = b * 1024 + t * 4;
    int s = 0;
#pragma unroll
    for (int j = 0; j < 4; j++) {
        int i = base + j;
        if (i < NN) s += g_deg[i];
    }
    __shared__ int red[256];
    red[t] = s;
    __syncthreads();
    for (int o = 128; o > 0; o >>= 1) {
        if (t < o) red[t] += red[t + o];
        __syncthreads();
    }
    if (t == 0) g_bsum[b] = red[0];
}

__global__ void scan2_k(int nb) {
    __shared__ int s[128];
    int t = threadIdx.x;
    s[t] = (t < nb) ? g_bsum[t] : 0;
    __syncthreads();
    if (t == 0) {
        int run = 0;
        for (int i = 0; i < nb; i++) { int v = s[i]; s[i] = run; run += v; }
        g_rowptr[NN] = run;
    }
    __syncthreads();
    if (t < nb) g_bsum[t] = s[t];
}

__global__ void scan3_k() {
    int b = blockIdx.x, t = threadIdx.x;
    int base = b * 1024 + t * 4;
    int v[4];
    int tot = 0;
#pragma unroll
    for (int j = 0; j < 4; j++) {
        int i = base + j;
        v[j] = (i < NN) ? g_deg[i] : 0;
        tot += v[j];
    }
    __shared__ int sc[256];
    sc[t] = tot;
    __syncthreads();
    for (int o = 1; o < 256; o <<= 1) {
        int x = (t >= o) ? sc[t - o] : 0;
        __syncthreads();
        sc[t] += x;
        __syncthreads();
    }
    int excl = sc[t] - tot + g_bsum[b];
#pragma unroll
    for (int j = 0; j < 4; j++) {
        int i = base + j;
        if (i < NN) { g_rowptr[i] = excl; g_pos[i] = excl; excl += v[j]; }
    }
}

__global__ void fill_k(const int* __restrict__ ei, int E) {
    int e = blockIdx.x * blockDim.x + threadIdx.x;
    if (e >= E) return;
    int s = ei[e], d = ei[E + e];
    if (s != d) {
        int slot = atomicAdd(&g_pos[d], 1);
        g_col[slot] = s;
    }
}

// ---------------- GEMM 1 (f32x2) + fused GAT1 scores + exp precompute ----------------
__global__ __launch_bounds__(256) void gemm1_k(const float* __restrict__ x,
                                               const float* __restrict__ W1,
                                               const float* __restrict__ att1) {
    __shared__ __align__(16) float sW[64 * 64];
    __shared__ float sAtt[128];
    for (int i = threadIdx.x; i < 4096; i += 256) sW[i] = W1[i];
    if (threadIdx.x < 128) sAtt[threadIdx.x] = att1[threadIdx.x];
    __syncthreads();
    int lane = threadIdx.x & 31;
    int gw = (blockIdx.x * blockDim.x + threadIdx.x) >> 5;
    int nw = (gridDim.x * blockDim.x) >> 5;
    int h = lane >> 2;
    int cc = (lane & 3) * 2;
    float ai0 = sAtt[h * 16 + cc],     ai1 = sAtt[h * 16 + cc + 1];
    float aj0 = sAtt[h * 16 + 8 + cc], aj1 = sAtt[h * 16 + 8 + cc + 1];
    for (int n = gw; n < NN; n += nw) {
        float2 xr = *(const float2*)&x[n * 64 + lane * 2];
        u64t acc; F2PACK(acc, 0.f, 0.f);
#pragma unroll
        for (int k2 = 0; k2 < 32; k2++) {
            float xa = __shfl_sync(0xffffffffu, xr.x, k2);
            float xb = __shfl_sync(0xffffffffu, xr.y, k2);
            u64t xaa, xbb;
            F2PACK(xaa, xa, xa);
            F2PACK(xbb, xb, xb);
            u64t w0 = *(const u64t*)&sW[(2 * k2) * 64 + lane * 2];
            F2FMA(acc, xaa, w0, acc);
            u64t w1 = *(const u64t*)&sW[(2 * k2 + 1) * 64 + lane * 2];
            F2FMA(acc, xbb, w1, acc);
        }
        float a0, a1;
        F2UNPACK(a0, a1, acc);
        *(__half2*)&g_xw1h[(size_t)n * 64 + lane * 2] = __floats2half2_rn(a0, a1);
        float si = a0 * ai0 + a1 * ai1;
        float sj = a0 * aj0 + a1 * aj1;
        si += __shfl_xor_sync(0xffffffffu, si, 1);
        si += __shfl_xor_sync(0xffffffffu, si, 2);
        sj += __shfl_xor_sync(0xffffffffu, sj, 1);
        sj += __shfl_xor_sync(0xffffffffu, sj, 2);
        if ((lane & 3) == 0) {
            g_s1dst[n * 8 + h] = si;
            g_s1pack[n * 8 + h] = make_float2(sj, __expf(0.2f * sj));
        }
    }
}

// ---------------- Encoder: warp per 2 nodes; weights shared across the pair ----------------
__device__ __forceinline__ void ln6r(float* o, const float* g, const float* b) {
    float mu = (o[0] + o[1] + o[2] + o[3] + o[4] + o[5]) * (1.f / 6.f);
    float d0 = o[0] - mu, d1 = o[1] - mu, d2 = o[2] - mu, d3 = o[3] - mu, d4 = o[4] - mu, d5 = o[5] - mu;
    float var = (d0 * d0 + d1 * d1 + d2 * d2 + d3 * d3 + d4 * d4 + d5 * d5) * (1.f / 6.f);
    float rs = rsqrtf(var + 1e-5f);
    o[0] = d0 * rs * g[0] + b[0];
    o[1] = d1 * rs * g[1] + b[1];
    o[2] = d2 * rs * g[2] + b[2];
    o[3] = d3 * rs * g[3] + b[3];
    o[4] = d4 * rs * g[4] + b[4];
    o[5] = d5 * rs * g[5] + b[5];
}

__global__ __launch_bounds__(256) void encoder_k(
    const float* __restrict__ ef,
    const float* __restrict__ Wq, const float* __restrict__ bq,
    const float* __restrict__ Wk, const float* __restrict__ bk,
    const float* __restrict__ Wv, const float* __restrict__ bv,
    const float* __restrict__ g0, const float* __restrict__ be0,
    const float* __restrict__ Wf1, const float* __restrict__ bf1,
    const float* __restrict__ Wf2, const float* __restrict__ bf2,
    const float* __restrict__ g1, const float* __restrict__ be1,
    const float* __restrict__ Wrep, const float* __restrict__ brep) {
    __shared__ __align__(16) float swf[688];
    __shared__ ulonglong2 sKV[8][2][32][3];
    int tid = threadIdx.x;
    const float SCALE = 0.40824829046386307f; // 1/sqrt(6)
    for (int i = tid; i < 688; i += 256) swf[i] = 0.f;
    __syncthreads();
    for (int i = tid; i < 60; i += 256) {
        int kk = i / 6, j = i % 6;
        int col = (j >> 1) + (j & 1) * 3;   // pair permute
        swf[kk * 8 + j] = Wq[kk * 6 + col];
        swf[80 + kk * 8 + j] = Wk[kk * 6 + col] * SCALE;
        swf[160 + kk * 8 + j] = Wv[kk * 6 + col];
    }
    for (int i = tid; i < 144; i += 256) swf[240 + i] = Wf1[i];
    for (int i = tid; i < 144; i += 256) {
        int jj = i / 6, j = i % 6;
        int col = (j >> 1) + (j & 1) * 3;
        swf[384 + jj * 8 + j] = Wf2[jj * 6 + col];
    }
    if (tid < 6) {
        int col = (tid >> 1) + (tid & 1) * 3;
        swf[576 + tid] = bq[col];
        swf[582 + tid] = bk[col] * SCALE;
        swf[588 + tid] = bv[col];
        swf[630 + tid] = bf2[col];
        swf[594 + tid] = g0[tid]; swf[600 + tid] = be0[tid];
        swf[636 + tid] = g1[tid]; swf[642 + tid] = be1[tid];
    }
    if (tid < 24) swf[606 + tid] = bf1[tid];
    if (tid < 32) swf[648 + tid] = Wrep[tid];
    if (tid == 0) swf[680] = brep[0];
    __syncthreads();

    int lane = tid & 31, w = tid >> 5;
    int gw = (blockIdx.x * blockDim.x + tid) >> 5;
    int nwarps = (gridDim.x * blockDim.x) >> 5;

    float g0r[6], be0r[6], g1r[6], be1r[6];
#pragma unroll
    for (int j = 0; j < 6; j++) {
        g0r[j] = swf[594 + j]; be0r[j] = swf[600 + j];
        g1r[j] = swf[636 + j]; be1r[j] = swf[642 + j];
    }
    float wr = swf[648 + lane];
    float brepv = swf[680];

    for (int n0 = gw * 2; n0 < NN; n0 += nwarps * 2) {
        const float* xrA = ef + (size_t)n0 * 320 + lane * 10;
        const float* xrB = xrA + 320;
        float2 a0_ = *(const float2*)xrA, a1_ = *(const float2*)(xrA + 2),
               a2_ = *(const float2*)(xrA + 4), a3_ = *(const float2*)(xrA + 6),
               a4_ = *(const float2*)(xrA + 8);
        float2 b0_ = *(const float2*)xrB, b1_ = *(const float2*)(xrB + 2),
               b2_ = *(const float2*)(xrB + 4), b3_ = *(const float2*)(xrB + 6),
               b4_ = *(const float2*)(xrB + 8);
        float xaA[10] = {a0_.x, a0_.y, a1_.x, a1_.y, a2_.x, a2_.y, a3_.x, a3_.y, a4_.x, a4_.y};
        float xaB[10] = {b0_.x, b0_.y, b1_.x, b1_.y, b2_.x, b2_.y, b3_.x, b3_.y, b4_.x, b4_.y};
        u64t bq0 = *(const u64t*)&swf[576], bq1 = *(const u64t*)&swf[578], bq2 = *(const u64t*)&swf[580];
        u64t bk0 = *(const u64t*)&swf[582], bk1 = *(const u64t*)&swf[584], bk2 = *(const u64t*)&swf[586];
        u64t bv0 = *(const u64t*)&swf[588], bv1 = *(const u64t*)&swf[590], bv2 = *(const u64t*)&swf[592];
        u64t qpA0 = bq0, qpA1 = bq1, qpA2 = bq2;
        u64t kpA0 = bk0, kpA1 = bk1, kpA2 = bk2;
        u64t vpA0 = bv0, vpA1 = bv1, vpA2 = bv2;
        u64t qpB0 = bq0, qpB1 = bq1, qpB2 = bq2;
        u64t kpB0 = bk0, kpB1 = bk1, kpB2 = bk2;
        u64t vpB0 = bv0, vpB1 = bv1, vpB2 = bv2;
#pragma unroll
        for (int kk = 0; kk < 10; kk++) {
            u64t xxA, xxB;
            F2PACK(xxA, xaA[kk], xaA[kk]);
            F2PACK(xxB, xaB[kk], xaB[kk]);
            ulonglong2 A = *(const ulonglong2*)&swf[kk * 8];
            u64t A2 = *(const u64t*)&swf[kk * 8 + 4];
            F2FMA(qpA0, xxA, A.x, qpA0); F2FMA(qpA1, xxA, A.y, qpA1); F2FMA(qpA2, xxA, A2, qpA2);
            F2FMA(qpB0, xxB, A.x, qpB0); F2FMA(qpB1, xxB, A.y, qpB1); F2FMA(qpB2, xxB, A2, qpB2);
            ulonglong2 B = *(const ulonglong2*)&swf[80 + kk * 8];
            u64t B2 = *(const u64t*)&swf[80 + kk * 8 + 4];
            F2FMA(kpA0, xxA, B.x, kpA0); F2FMA(kpA1, xxA, B.y, kpA1); F2FMA(kpA2, xxA, B2, kpA2);
            F2FMA(kpB0, xxB, B.x, kpB0); F2FMA(kpB1, xxB, B.y, kpB1); F2FMA(kpB2, xxB, B2, kpB2);
            ulonglong2 C = *(const ulonglong2*)&swf[160 + kk * 8];
            u64t C2 = *(const u64t*)&swf[160 + kk * 8 + 4];
            F2FMA(vpA0, xxA, C.x, vpA0); F2FMA(vpA1, xxA, C.y, vpA1); F2FMA(vpA2, xxA, C2, vpA2);
            F2FMA(vpB0, xxB, C.x, vpB0); F2FMA(vpB1, xxB, C.y, vpB1); F2FMA(vpB2, xxB, C2, vpB2);
        }
        {
            ulonglong2 m;
            m.x = kpA0; m.y = kpA1; sKV[w][0][lane][0] = m;
            m.x = kpA2; m.y = vpA0; sKV[w][0][lane][1] = m;
            m.x = vpA1; m.y = vpA2; sKV[w][0][lane][2] = m;
            m.x = kpB0; m.y = kpB1; sKV[w][1][lane][0] = m;
            m.x = kpB2; m.y = vpB0; sKV[w][1][lane][1] = m;
            m.x = vpB1; m.y = vpB2; sKV[w][1][lane][2] = m;
        }
        __syncwarp();
        float oA[6], oB[6];
        {
            u64t lpA, acA0, acA1, acA2, lpB, acB0, acB1, acB2;
            F2PACK(lpA, 0.f, 0.f);
            acA0 = lpA; acA1 = lpA; acA2 = lpA;
            lpB = lpA; acB0 = lpA; acB1 = lpA; acB2 = lpA;
#pragma unroll
            for (int tp = 0; tp < 32; tp++) {
                ulonglong2 ma0 = sKV[w][0][tp][0];
                ulonglong2 ma1 = sKV[w][0][tp][1];
                ulonglong2 ma2 = sKV[w][0][tp][2];
                ulonglong2 mb0 = sKV[w][1][tp][0];
                ulonglong2 mb1 = sKV[w][1][tp][1];
                ulonglong2 mb2 = sKV[w][1][tp][2];
                u64t tA, tB;
                F2MUL(tA, qpA2, ma1.x);
                F2FMA(tA, qpA1, ma0.y, tA);
                F2FMA(tA, qpA0, ma0.x, tA);
                F2MUL(tB, qpB2, mb1.x);
                F2FMA(tB, qpB1, mb0.y, tB);
                F2FMA(tB, qpB0, mb0.x, tB);
                float sA0, sA1, sB0, sB1;
                F2UNPACK(sA0, sA1, tA);
                F2UNPACK(sB0, sB1, tB);
                float eA0 = __expf(sA0), eA1 = __expf(sA1);
                float eB0 = __expf(sB0), eB1 = __expf(sB1);
                u64t epA, epB;
                F2PACK(epA, eA0, eA1);
                F2PACK(epB, eB0, eB1);
                F2ADD(lpA, lpA, epA);
                F2FMA(acA0, epA, ma1.y, acA0);
                F2FMA(acA1, epA, ma2.x, acA1);
                F2FMA(acA2, epA, ma2.y, acA2);
                F2ADD(lpB, lpB, epB);
                F2FMA(acB0, epB, mb1.y, acB0);
                F2FMA(acB1, epB, mb2.x, acB1);
                F2FMA(acB2, epB, mb2.y, acB2);
            }
            float l0, l1, x00, x10, x01, x11, x02, x12, q0, q3, q1, q4, q2, q5;
            F2UNPACK(l0, l1, lpA);
            F2UNPACK(x00, x10, acA0);
            F2UNPACK(x01, x11, acA1);
            F2UNPACK(x02, x12, acA2);
            F2UNPACK(q0, q3, qpA0);
            F2UNPACK(q1, q4, qpA1);
            F2UNPACK(q2, q5, qpA2);
            float i0 = 1.f / l0, i1 = 1.f / l1;
            oA[0] = q0 + x00 * i0; oA[1] = q1 + x01 * i0; oA[2] = q2 + x02 * i0;
            oA[3] = q3 + x10 * i1; oA[4] = q4 + x11 * i1; oA[5] = q5 + x12 * i1;
            F2UNPACK(l0, l1, lpB);
            F2UNPACK(x00, x10, acB0);
            F2UNPACK(x01, x11, acB1);
            F2UNPACK(x02, x12, acB2);
            F2UNPACK(q0, q3, qpB0);
            F2UNPACK(q1, q4, qpB1);
            F2UNPACK(q2, q5, qpB2);
            i0 = 1.f / l0; i1 = 1.f / l1;
            oB[0] = q0 + x00 * i0; oB[1] = q1 + x01 * i0; oB[2] = q2 + x02 * i0;
            oB[3] = q3 + x10 * i1; oB[4] = q4 + x11 * i1; oB[5] = q5 + x12 * i1;
        }
        __syncwarp();
        ln6r(oA, g0r, be0r);
        ln6r(oB, g0r, be0r);
        u64t hpA[12], hpB[12];
#pragma unroll
        for (int j = 0; j < 12; j++) {
            u64t t = *(const u64t*)&swf[606 + 2 * j];
            hpA[j] = t; hpB[j] = t;
        }
#pragma unroll
        for (int kk = 0; kk < 6; kk++) {
            u64t ooA, ooB;
            F2PACK(ooA, oA[kk], oA[kk]);
            F2PACK(ooB, oB[kk], oB[kk]);
            const ulonglong2* r = (const ulonglong2*)&swf[240 + kk * 24];
#pragma unroll
            for (int i = 0; i < 6; i++) {
                ulonglong2 rv = r[i];
                F2FMA(hpA[2 * i], ooA, rv.x, hpA[2 * i]);
                F2FMA(hpA[2 * i + 1], ooA, rv.y, hpA[2 * i + 1]);
                F2FMA(hpB[2 * i], ooB, rv.x, hpB[2 * i]);
                F2FMA(hpB[2 * i + 1], ooB, rv.y, hpB[2 * i + 1]);
            }
        }
        u64t fpA0 = *(const u64t*)&swf[630], fpA1 = *(const u64t*)&swf[632], fpA2 = *(const u64t*)&swf[634];
        u64t fpB0 = fpA0, fpB1 = fpA1, fpB2 = fpA2;
#pragma unroll
        for (int j = 0; j < 12; j++) {
            float la, ha, lb, hb;
            F2UNPACK(la, ha, hpA[j]);
            F2UNPACK(lb, hb, hpB[j]);
            la = fmaxf(la, 0.f); ha = fmaxf(ha, 0.f);
            lb = fmaxf(lb, 0.f); hb = fmaxf(hb, 0.f);
            u64t hAlo, hAhi, hBlo, hBhi;
            F2PACK(hAlo, la, la); F2PACK(hAhi, ha, ha);
            F2PACK(hBlo, lb, lb); F2PACK(hBhi, hb, hb);
            int jj = 2 * j;
            ulonglong2 rv0 = *(const ulonglong2*)&swf[384 + jj * 8];
            u64t rv0b = *(const u64t*)&swf[384 + jj * 8 + 4];
            ulonglong2 rv1 = *(const ulonglong2*)&swf[384 + (jj + 1) * 8];
            u64t rv1b = *(const u64t*)&swf[384 + (jj + 1) * 8 + 4];
            F2FMA(fpA0, hAlo, rv0.x, fpA0); F2FMA(fpA1, hAlo, rv0.y, fpA1); F2FMA(fpA2, hAlo, rv0b, fpA2);
            F2FMA(fpA0, hAhi, rv1.x, fpA0); F2FMA(fpA1, hAhi, rv1.y, fpA1); F2FMA(fpA2, hAhi, rv1b, fpA2);
            F2FMA(fpB0, hBlo, rv0.x, fpB0); F2FMA(fpB1, hBlo, rv0.y, fpB1); F2FMA(fpB2, hBlo, rv0b, fpB2);
            F2FMA(fpB0, hBhi, rv1.x, fpB0); F2FMA(fpB1, hBhi, rv1.y, fpB1); F2FMA(fpB2, hBhi, rv1b, fpB2);
        }
        {
            float f0, f3, f1, f4, f2, f5;
            F2UNPACK(f0, f3, fpA0);
            F2UNPACK(f1, f4, fpA1);
            F2UNPACK(f2, f5, fpA2);
            oA[0] += f0; oA[1] += f1; oA[2] += f2; oA[3] += f3; oA[4] += f4; oA[5] += f5;
            F2UNPACK(f0, f3, fpB0);
            F2UNPACK(f1, f4, fpB1);
            F2UNPACK(f2, f5, fpB2);
            oB[0] += f0; oB[1] += f1; oB[2] += f2; oB[3] += f3; oB[4] += f4; oB[5] += f5;
        }
        ln6r(oA, g1r, be1r);
        ln6r(oB, g1r, be1r);
#pragma unroll
        for (int j = 0; j < 6; j++) {
            float cA = oA[j] * wr;
            float cB = oB[j] * wr;
            cA += __shfl_xor_sync(0xffffffffu, cA, 16);
            cB += __shfl_xor_sync(0xffffffffu, cB, 16);
            cA += __shfl_xor_sync(0xffffffffu, cA, 8);
            cB += __shfl_xor_sync(0xffffffffu, cB, 8);
            cA += __shfl_xor_sync(0xffffffffu, cA, 4);
            cB += __shfl_xor_sync(0xffffffffu, cB, 4);
            cA += __shfl_xor_sync(0xffffffffu, cA, 2);
            cB += __shfl_xor_sync(0xffffffffu, cB, 2);
            cA += __shfl_xor_sync(0xffffffffu, cA, 1);
            cB += __shfl_xor_sync(0xffffffffu, cB, 1);
            if (lane == 0) {
                g_xt[(size_t)n0 * 6 + j] = cA + brepv;
                g_xt[(size_t)(n0 + 1) * 6 + j] = cB + brepv;
            }
        }
    }
}

// ---------------- layer2a: GAT1 aggregation + GEMM2 over the 64 h1 features ----------------
__global__ __launch_bounds__(256) void layer2a_k(const float* __restrict__ b1,
                                                 const float* __restrict__ W2) {
    __shared__ __align__(16) float sW[64 * 80];
    __shared__ float sB1[64];
    for (int i = threadIdx.x; i < 5120; i += 256) sW[i] = W2[i];
    if (threadIdx.x < 64) sB1[threadIdx.x] = b1[threadIdx.x];
    __syncthreads();
    int lane = threadIdx.x & 31;
    int gw = (blockIdx.x * blockDim.x + threadIdx.x) >> 5;
    int nw = (gridDim.x * blockDim.x) >> 5;
    int hl = lane & 7;
    int eidx = lane >> 3;
    int c0 = lane * 2;
    int hh = lane >> 2;
    int cL = 2 * lane;
    int cH = 64 + 2 * lane;
    bool hiActive = lane < 8;
    float b1lo = sB1[c0], b1hi = sB1[c0 + 1];

    for (int d = gw; d < NN; d += nw) {
        int start = g_rowptr[d], deg = g_rowptr[d + 1] - start;
        float sdd = g_s1dst[d * 8 + hl];
        float fd1 = __expf(sdd), fd02 = __expf(0.2f * sdd);
        float2 ps = g_s1pack[d * 8 + hl];
        float eself;
        {
            float t = ps.y * ps.y;
            float es = t * t * ps.y;
            eself = (sdd + ps.x >= 0.f) ? fd1 * es : fd02 * ps.y;
        }
        float den = (eidx == 0) ? eself : 0.f;
        float wself = __shfl_sync(0xffffffffu, eself, hh);
        float2 xs = __half22float2(*(const __half2*)&g_xw1h[(size_t)d * 64 + c0]);
        float acc0 = wself * xs.x, acc1 = wself * xs.y;
        for (int base = 0; base < deg; base += 4) {
            int e = base + eidx;
            float wv = 0.f;
            int scol = 0;
            if (e < deg) {
                scol = g_col[start + e];
                float2 p = g_s1pack[scol * 8 + hl];
                float t = p.y * p.y;
                float es = t * t * p.y;
                wv = (sdd + p.x >= 0.f) ? fd1 * es : fd02 * p.y;
            }
            den += wv;
#pragma unroll
            for (int i = 0; i < 4; i++) {
                if (base + i < deg) {
                    int s = __shfl_sync(0xffffffffu, scol, i * 8);
                    float wgt = __shfl_sync(0xffffffffu, wv, i * 8 + hh);
                    float2 xv = __half22float2(*(const __half2*)&g_xw1h[(size_t)s * 64 + c0]);
                    acc0 += wgt * xv.x;
                    acc1 += wgt * xv.y;
                }
            }
        }
        den += __shfl_xor_sync(0xffffffffu, den, 8);
        den += __shfl_xor_sync(0xffffffffu, den, 16);
        float invden = 1.f / den;
        float inv = __shfl_sync(0xffffffffu, invden, hh);
        float v0 = acc0 * inv + b1lo, v1 = acc1 * inv + b1hi;
        v0 = v0 > 0.f ? v0 : (__expf(v0) - 1.f);
        v1 = v1 > 0.f ? v1 : (__expf(v1) - 1.f);

        // GEMM2 partial (64 h1 features only), fp32 output
        u64t a0p, a1p;
        F2PACK(a0p, 0.f, 0.f);
        a1p = a0p;
#pragma unroll
        for (int p = 0; p < 32; p++) {
            float xv0 = __shfl_sync(0xffffffffu, v0, p);
            float xv1 = __shfl_sync(0xffffffffu, v1, p);
            u64t xx0, xx1;
            F2PACK(xx0, xv0, xv0);
            F2PACK(xx1, xv1, xv1);
            u64t w0 = *(const u64t*)&sW[(2 * p) * 80 + cL];
            F2FMA(a0p, xx0, w0, a0p);
            u64t w1 = *(const u64t*)&sW[(2 * p + 1) * 80 + cL];
            F2FMA(a0p, xx1, w1, a0p);
            if (hiActive) {
                u64t wh0 = *(const u64t*)&sW[(2 * p) * 80 + cH];
                F2FMA(a1p, xx0, wh0, a1p);
                u64t wh1 = *(const u64t*)&sW[(2 * p + 1) * 80 + cH];
                F2FMA(a1p, xx1, wh1, a1p);
            }
        }
        float aL0, aL1;
        F2UNPACK(aL0, aL1, a0p);
        *(float2*)&g_xw2p[(size_t)d * 80 + cL] = make_float2(aL0, aL1);
        if (hiActive) {
            float aH0, aH1;
            F2UNPACK(aH0, aH1, a1p);
            *(float2*)&g_xw2p[(size_t)d * 80 + cH] = make_float2(aH0, aH1);
        }
    }
}

// ---------------- layer2b: add encoder rank-6 update + fp16 convert + GAT2 scores ----------------
__global__ __launch_bounds__(256) void layer2b_k(const float* __restrict__ W2,
                                                 const float* __restrict__ att2) {
    __shared__ __align__(16) float sWt[6 * 80];   // W2 rows 64..69
    __shared__ float sAtt[160];
    __shared__ float srow[8][80];
    for (int i = threadIdx.x; i < 480; i += 256) sWt[i] = W2[64 * 80 + i];
    if (threadIdx.x < 160) sAtt[threadIdx.x] = att2[threadIdx.x];
    __syncthreads();
    int lane = threadIdx.x & 31;
    int w = threadIdx.x >> 5;
    int gw = (blockIdx.x * blockDim.x + threadIdx.x) >> 5;
    int nw = (gridDim.x * blockDim.x) >> 5;
    int cL = 2 * lane;
    int cH = 64 + 2 * lane;
    bool hiActive = lane < 8;
    for (int d = gw; d < NN; d += nw) {
        float xtv = (lane < 6) ? g_xt[(size_t)d * 6 + lane] : 0.f;
        u64t a0p = *(const u64t*)&g_xw2p[(size_t)d * 80 + cL];
        u64t a1p = 0;
        if (hiActive) a1p = *(const u64t*)&g_xw2p[(size_t)d * 80 + cH];
#pragma unroll
        for (int j = 0; j < 6; j++) {
            float xv = __shfl_sync(0xffffffffu, xtv, j);
            u64t xx; F2PACK(xx, xv, xv);
            u64t w0 = *(const u64t*)&sWt[j * 80 + cL];
            F2FMA(a0p, xx, w0, a0p);
            if (hiActive) {
                u64t wh = *(const u64t*)&sWt[j * 80 + cH];
                F2FMA(a1p, xx, wh, a1p);
            }
        }
        float aL0, aL1;
        F2UNPACK(aL0, aL1, a0p);
        *(__half2*)&g_xw2h[(size_t)d * 80 + cL] = __floats2half2_rn(aL0, aL1);
        srow[w][cL] = aL0;
        srow[w][cL + 1] = aL1;
        if (hiActive) {
            float aH0, aH1;
            F2UNPACK(aH0, aH1, a1p);
            *(__half2*)&g_xw2h[(size_t)d * 80 + cH] = __floats2half2_rn(aH0, aH1);
            srow[w][cH] = aH0;
            srow[w][cH + 1] = aH1;
        }
        __syncwarp();
        if (lane < 16) {
            int h = lane >> 1, part = lane & 1;
            const float* r = srow[w] + h * 10;
            const float* at = sAtt + h * 20 + part * 10;
            float s = 0.f;
#pragma unroll
            for (int c = 0; c < 10; c++) s += r[c] * at[c];
            if (part == 0) {
                g_s2dst[d * 8 + h] = s;
            } else {
                g_s2pack[d * 8 + h] = make_float2(s, __expf(0.2f * s));
            }
        }
        __syncwarp();
    }
}

// ---------------- GAT2 aggregation: factored exp (float2 pack) + fp16 rows ----------------
__global__ __launch_bounds__(256) void gat2_agg_k(const float* __restrict__ b2,
                                                  float* __restrict__ out) {
    __shared__ float sacc[8][80];
    __shared__ float sval[8][16];
    int gw = (blockIdx.x * blockDim.x + threadIdx.x) >> 5;
    if (gw >= NN) return;
    int lane = threadIdx.x & 31;
    int w = (threadIdx.x >> 5);
    int d = gw;
    int start = g_rowptr[d], deg = g_rowptr[d + 1] - start;
    int hl = lane & 7;
    int eidx = lane >> 3;
    float sdd = g_s2dst[d * 8 + hl];
    float fd1 = __expf(sdd), fd02 = __expf(0.2f * sdd);
    float2 ps = g_s2pack[d * 8 + hl];
    float eself;
    {
        float t = ps.y * ps.y;
        float es = t * t * ps.y;
        eself = (sdd + ps.x >= 0.f) ? fd1 * es : fd02 * ps.y;
    }
    float den = (eidx == 0) ? eself : 0.f;
    int h0 = lane / 10;
    int h1 = (lane + 32) / 10;
    int h2 = (lane + 64) / 10;
    int i2 = 64 + (lane & 15);
    float ws0 = __shfl_sync(0xffffffffu, eself, h0);
    float ws1 = __shfl_sync(0xffffffffu, eself, h1);
    float ws2 = __shfl_sync(0xffffffffu, eself, h2);
    const __half* xd = &g_xw2h[(size_t)d * 80];
    float acc0 = ws0 * __half2float(xd[lane]);
    float acc1 = ws1 * __half2float(xd[32 + lane]);
    float acc2 = ws2 * __half2float(xd[i2]);
    for (int base = 0; base < deg; base += 4) {
        int e = base + eidx;
        float wv = 0.f;
        int scol = 0;
        if (e < deg) {
            scol = g_col[start + e];
            float2 p = g_s2pack[scol * 8 + hl];
            float t = p.y * p.y;
            float es = t * t * p.y;
            wv = (sdd + p.x >= 0.f) ? fd1 * es : fd02 * p.y;
        }
        den += wv;
#pragma unroll
        for (int i = 0; i < 4; i++) {
            if (base + i < deg) {
                int s = __shfl_sync(0xffffffffu, scol, i * 8);
                float w0 = __shfl_sync(0xffffffffu, wv, i * 8 + h0);
                float w1 = __shfl_sync(0xffffffffu, wv, i * 8 + h1);
                float w2 = __shfl_sync(0xffffffffu, wv, i * 8 + h2);
                const __half* xr = &g_xw2h[(size_t)s * 80];
                acc0 += w0 * __half2float(xr[lane]);
                acc1 += w1 * __half2float(xr[32 + lane]);
                acc2 += w2 * __half2float(xr[i2]);
            }
        }
    }
    den += __shfl_xor_sync(0xffffffffu, den, 8);
    den += __shfl_xor_sync(0xffffffffu, den, 16);
    float invden = 1.f / den;
    float iv0 = __shfl_sync(0xffffffffu, invden, h0);
    float iv1 = __shfl_sync(0xffffffffu, invden, h1);
    float iv2 = __shfl_sync(0xffffffffu, invden, h2);
    sacc[w][lane] = acc0 * iv0;
    sacc[w][32 + lane] = acc1 * iv1;
    if (lane < 16) sacc[w][i2] = acc2 * iv2;
    __syncwarp();
    if (lane < 10) {
        float s = 0.f;
#pragma unroll
        for (int h = 0; h < 8; h++) s += sacc[w][h * 10 + lane];
        sval[w][lane] = s * 0.125f + b2[lane];
    }
    __syncwarp();
    if (lane < 10) {
        float mx = -INFINITY;
#pragma unroll
        for (int c = 0; c < 10; c++) mx = fmaxf(mx, sval[w][c]);
        float se = 0.f;
#pragma unroll
        for (int c = 0; c < 10; c++) se += __expf(sval[w][c] - mx);
        out[(size_t)d * 10 + lane] = sval[w][lane] - mx - logf(se);
    }
}

// ---------------- launch ----------------
extern "C" void kernel_launch(void* const* d_in, const int* in_sizes, int n_in,
                              void* d_out, int out_size) {
    const float* x    = (const float*)d_in[0];
    const int*   ei   = (const int*)d_in[1];
    const float* ef   = (const float*)d_in[2];
    const float* W1   = (const float*)d_in[3];
    const float* att1 = (const float*)d_in[4];
    const float* b1   = (const float*)d_in[5];
    const float* W2   = (const float*)d_in[6];
    const float* att2 = (const float*)d_in[7];
    const float* b2   = (const float*)d_in[8];
    const float* Wq   = (const float*)d_in[9];
    const float* bq   = (const float*)d_in[10];
    const float* Wk   = (const float*)d_in[11];
    const float* bk   = (const float*)d_in[12];
    const float* Wv   = (const float*)d_in[13];
    const float* bv   = (const float*)d_in[14];
    const float* g0   = (const float*)d_in[15];
    const float* be0  = (const float*)d_in[16];
    const float* Wf1  = (const float*)d_in[17];
    const float* bf1  = (const float*)d_in[18];
    const float* Wf2  = (const float*)d_in[19];
    const float* bf2  = (const float*)d_in[20];
    const float* g1   = (const float*)d_in[21];
    const float* be1  = (const float*)d_in[22];
    const float* Wrep = (const float*)d_in[23];
    const float* brep = (const float*)d_in[24];
    float* out = (float*)d_out;
    int E = in_sizes[1] / 2;

    static cudaStream_t sB = 0, sC = 0;
    static cudaEvent_t evFork = 0, evB = 0, evC = 0;
    if (sB == 0) {
        cudaStreamCreateWithFlags(&sB, cudaStreamNonBlocking);
        cudaStreamCreateWithFlags(&sC, cudaStreamNonBlocking);
        cudaEventCreateWithFlags(&evFork, cudaEventDisableTiming);
        cudaEventCreateWithFlags(&evB, cudaEventDisableTiming);
        cudaEventCreateWithFlags(&evC, cudaEventDisableTiming);
    }

    cudaEventRecord(evFork, 0);
    cudaStreamWaitEvent(sB, evFork, 0);
    cudaStreamWaitEvent(sC, evFork, 0);

    gemm1_k<<<1184, 256, 0, sB>>>(x, W1, att1);
    cudaEventRecord(evB, sB);

    encoder_k<<<1184, 256, 0, sC>>>(ef, Wq, bq, Wk, bk, Wv, bv, g0, be0,
                                    Wf1, bf1, Wf2, bf2, g1, be1, Wrep, brep);
    cudaEventRecord(evC, sC);

    zero_deg_k<<<(NN + 255) / 256, 256>>>();
    hist_k<<<(E + 255) / 256, 256>>>(ei, E);
    scan1_k<<<(NN + 1023) / 1024, 256>>>();
    scan2_k<<<1, 128>>>((NN + 1023) / 1024);
    scan3_k<<<(NN + 1023) / 1024, 256>>>();
    fill_k<<<(E + 255) / 256, 256>>>(ei, E);

    // layer2a needs only gemm1 + CSR (not the encoder)
    cudaStreamWaitEvent(0, evB, 0);
    layer2a_k<<<1184, 256>>>(b1, W2);

    // layer2b is the only kernel that waits on the encoder
    cudaStreamWaitEvent(0, evC, 0);
    layer2b_k<<<1184, 256>>>(W2, att2);
    gat2_agg_k<<<(NN + 7) / 8, 256>>>(b2, out);
}

// round 17
// speedup vs baseline: 1.0470x; 1.0470x over previous
#include <cuda_runtime.h>
#include <cuda_fp16.h>
#include <math.h>

#define NN 100000
#define EE 1600000

typedef unsigned long long u64t;

#define F2PACK(d, lo, hi) asm("mov.b64 %0, {%1, %2};" : "=l"(d) : "f"(lo), "f"(hi))
#define F2UNPACK(lo, hi, v) asm("mov.b64 {%0, %1}, %2;" : "=f"(lo), "=f"(hi) : "l"(v))
#define F2FMA(d, a, b, c) asm("fma.rn.f32x2 %0, %1, %2, %3;" : "=l"(d) : "l"(a), "l"(b), "l"(c))
#define F2MUL(d, a, b) asm("mul.rn.f32x2 %0, %1, %2;" : "=l"(d) : "l"(a), "l"(b))
#define F2ADD(d, a, b) asm("add.rn.f32x2 %0, %1, %2;" : "=l"(d) : "l"(a), "l"(b))

// ---------------- scratch ----------------
__device__ __align__(16) __half g_xw1h[NN * 64];
__device__ __align__(16) float g_xt[NN * 6];       // encoder output
__device__ __align__(16) __half g_xw2h[NN * 80];
__device__ float g_s1dst[NN * 8];
__device__ float g_s2dst[NN * 8];
__device__ __align__(8) float2 g_s1pack[NN * 8];   // (s_src, exp(0.2 s_src))
__device__ __align__(8) float2 g_s2pack[NN * 8];
__device__ int g_deg[NN];
__device__ int g_rowptr[NN + 1];
__device__ int g_pos[NN];
__device__ int g_col[EE];
__device__ int g_bsum[128];

// ---------------- CSR build ----------------
__global__ void zero_deg_k() {
    int i = blockIdx.x * blockDim.x + threadIdx.x;
    if (i < NN) g_deg[i] = 0;
}

__global__ void hist_k(const int* __restrict__ ei, int E) {
    int e = blockIdx.x * blockDim.x + threadIdx.x;
    if (e >= E) return;
    int s = ei[e], d = ei[E + e];
    if (s != d) atomicAdd(&g_deg[d], 1);
}

__global__ void scan1_k() {
    int b = blockIdx.x, t = threadIdx.x;
    int base = b * 1024 + t * 4;
    int s = 0;
#pragma unroll
    for (int j = 0; j < 4; j++) {
        int i = base + j;
        if (i < NN) s += g_deg[i];
    }
    __shared__ int red[256];
    red[t] = s;
    __syncthreads();
    for (int o = 128; o > 0; o >>= 1) {
        if (t < o) red[t] += red[t + o];
        __syncthreads();
    }
    if (t == 0) g_bsum[b] = red[0];
}

__global__ void scan2_k(int nb) {
    __shared__ int s[128];
    int t = threadIdx.x;
    s[t] = (t < nb) ? g_bsum[t] : 0;
    __syncthreads();
    if (t == 0) {
        int run = 0;
        for (int i = 0; i < nb; i++) { int v = s[i]; s[i] = run; run += v; }
        g_rowptr[NN] = run;
    }
    __syncthreads();
    if (t < nb) g_bsum[t] = s[t];
}

__global__ void scan3_k() {
    int b = blockIdx.x, t = threadIdx.x;
    int base = b * 1024 + t * 4;
    int v[4];
    int tot = 0;
#pragma unroll
    for (int j = 0; j < 4; j++) {
        int i = base + j;
        v[j] = (i < NN) ? g_deg[i] : 0;
        tot += v[j];
    }
    __shared__ int sc[256];
    sc[t] = tot;
    __syncthreads();
    for (int o = 1; o < 256; o <<= 1) {
        int x = (t >= o) ? sc[t - o] : 0;
        __syncthreads();
        sc[t] += x;
        __syncthreads();
    }
    int excl = sc[t] - tot + g_bsum[b];
#pragma unroll
    for (int j = 0; j < 4; j++) {
        int i = base + j;
        if (i < NN) { g_rowptr[i] = excl; g_pos[i] = excl; excl += v[j]; }
    }
}

__global__ void fill_k(const int* __restrict__ ei, int E) {
    int e = blockIdx.x * blockDim.x + threadIdx.x;
    if (e >= E) return;
    int s = ei[e], d = ei[E + e];
    if (s != d) {
        int slot = atomicAdd(&g_pos[d], 1);
        g_col[slot] = s;
    }
}

// ---------------- GEMM 1 (f32x2) + fused GAT1 scores + exp precompute ----------------
__global__ __launch_bounds__(256) void gemm1_k(const float* __restrict__ x,
                                               const float* __restrict__ W1,
                                               const float* __restrict__ att1) {
    __shared__ __align__(16) float sW[64 * 64];
    __shared__ float sAtt[128];
    for (int i = threadIdx.x; i < 4096; i += 256) sW[i] = W1[i];
    if (threadIdx.x < 128) sAtt[threadIdx.x] = att1[threadIdx.x];
    __syncthreads();
    int lane = threadIdx.x & 31;
    int gw = (blockIdx.x * blockDim.x + threadIdx.x) >> 5;
    int nw = (gridDim.x * blockDim.x) >> 5;
    int h = lane >> 2;
    int cc = (lane & 3) * 2;
    float ai0 = sAtt[h * 16 + cc],     ai1 = sAtt[h * 16 + cc + 1];
    float aj0 = sAtt[h * 16 + 8 + cc], aj1 = sAtt[h * 16 + 8 + cc + 1];
    for (int n = gw; n < NN; n += nw) {
        float2 xr = *(const float2*)&x[n * 64 + lane * 2];
        u64t acc; F2PACK(acc, 0.f, 0.f);
#pragma unroll
        for (int k2 = 0; k2 < 32; k2++) {
            float xa = __shfl_sync(0xffffffffu, xr.x, k2);
            float xb = __shfl_sync(0xffffffffu, xr.y, k2);
            u64t xaa, xbb;
            F2PACK(xaa, xa, xa);
            F2PACK(xbb, xb, xb);
            u64t w0 = *(const u64t*)&sW[(2 * k2) * 64 + lane * 2];
            F2FMA(acc, xaa, w0, acc);
            u64t w1 = *(const u64t*)&sW[(2 * k2 + 1) * 64 + lane * 2];
            F2FMA(acc, xbb, w1, acc);
        }
        float a0, a1;
        F2UNPACK(a0, a1, acc);
        *(__half2*)&g_xw1h[(size_t)n * 64 + lane * 2] = __floats2half2_rn(a0, a1);
        float si = a0 * ai0 + a1 * ai1;
        float sj = a0 * aj0 + a1 * aj1;
        si += __shfl_xor_sync(0xffffffffu, si, 1);
        si += __shfl_xor_sync(0xffffffffu, si, 2);
        sj += __shfl_xor_sync(0xffffffffu, sj, 1);
        sj += __shfl_xor_sync(0xffffffffu, sj, 2);
        if ((lane & 3) == 0) {
            g_s1dst[n * 8 + h] = si;
            g_s1pack[n * 8 + h] = make_float2(sj, __expf(0.2f * sj));
        }
    }
}

// ---------------- Encoder: warp per 2 nodes; occupancy-forced variant ----------------
__device__ __forceinline__ void ln6r(float* o, const float* g, const float* b) {
    float mu = (o[0] + o[1] + o[2] + o[3] + o[4] + o[5]) * (1.f / 6.f);
    float d0 = o[0] - mu, d1 = o[1] - mu, d2 = o[2] - mu, d3 = o[3] - mu, d4 = o[4] - mu, d5 = o[5] - mu;
    float var = (d0 * d0 + d1 * d1 + d2 * d2 + d3 * d3 + d4 * d4 + d5 * d5) * (1.f / 6.f);
    float rs = rsqrtf(var + 1e-5f);
    o[0] = d0 * rs * g[0] + b[0];
    o[1] = d1 * rs * g[1] + b[1];
    o[2] = d2 * rs * g[2] + b[2];
    o[3] = d3 * rs * g[3] + b[3];
    o[4] = d4 * rs * g[4] + b[4];
    o[5] = d5 * rs * g[5] + b[5];
}

__global__ __launch_bounds__(256, 3) void encoder_k(
    const float* __restrict__ ef,
    const float* __restrict__ Wq, const float* __restrict__ bq,
    const float* __restrict__ Wk, const float* __restrict__ bk,
    const float* __restrict__ Wv, const float* __restrict__ bv,
    const float* __restrict__ g0, const float* __restrict__ be0,
    const float* __restrict__ Wf1, const float* __restrict__ bf1,
    const float* __restrict__ Wf2, const float* __restrict__ bf2,
    const float* __restrict__ g1, const float* __restrict__ be1,
    const float* __restrict__ Wrep, const float* __restrict__ brep) {
    __shared__ __align__(16) float swf[688];
    __shared__ ulonglong2 sKV[8][2][32][3];
    int tid = threadIdx.x;
    const float SCALE = 0.40824829046386307f; // 1/sqrt(6)
    for (int i = tid; i < 688; i += 256) swf[i] = 0.f;
    __syncthreads();
    for (int i = tid; i < 60; i += 256) {
        int kk = i / 6, j = i % 6;
        int col = (j >> 1) + (j & 1) * 3;   // pair permute
        swf[kk * 8 + j] = Wq[kk * 6 + col];
        swf[80 + kk * 8 + j] = Wk[kk * 6 + col] * SCALE;
        swf[160 + kk * 8 + j] = Wv[kk * 6 + col];
    }
    for (int i = tid; i < 144; i += 256) swf[240 + i] = Wf1[i];
    for (int i = tid; i < 144; i += 256) {
        int jj = i / 6, j = i % 6;
        int col = (j >> 1) + (j & 1) * 3;
        swf[384 + jj * 8 + j] = Wf2[jj * 6 + col];
    }
    if (tid < 6) {
        int col = (tid >> 1) + (tid & 1) * 3;
        swf[576 + tid] = bq[col];
        swf[582 + tid] = bk[col] * SCALE;
        swf[588 + tid] = bv[col];
        swf[630 + tid] = bf2[col];
        swf[594 + tid] = g0[tid]; swf[600 + tid] = be0[tid];
        swf[636 + tid] = g1[tid]; swf[642 + tid] = be1[tid];
    }
    if (tid < 24) swf[606 + tid] = bf1[tid];
    if (tid < 32) swf[648 + tid] = Wrep[tid];
    if (tid == 0) swf[680] = brep[0];
    __syncthreads();

    int lane = tid & 31, w = tid >> 5;
    int gw = (blockIdx.x * blockDim.x + tid) >> 5;
    int nwarps = (gridDim.x * blockDim.x) >> 5;

    float g0r[6], be0r[6], g1r[6], be1r[6];
#pragma unroll
    for (int j = 0; j < 6; j++) {
        g0r[j] = swf[594 + j]; be0r[j] = swf[600 + j];
        g1r[j] = swf[636 + j]; be1r[j] = swf[642 + j];
    }
    float wr = swf[648 + lane];
    float brepv = swf[680];

    for (int n0 = gw * 2; n0 < NN; n0 += nwarps * 2) {
        const float* xrA = ef + (size_t)n0 * 320 + lane * 10;
        const float* xrB = xrA + 320;
        float2 a0_ = *(const float2*)xrA, a1_ = *(const float2*)(xrA + 2),
               a2_ = *(const float2*)(xrA + 4), a3_ = *(const float2*)(xrA + 6),
               a4_ = *(const float2*)(xrA + 8);
        float2 b0_ = *(const float2*)xrB, b1_ = *(const float2*)(xrB + 2),
               b2_ = *(const float2*)(xrB + 4), b3_ = *(const float2*)(xrB + 6),
               b4_ = *(const float2*)(xrB + 8);
        float xaA[10] = {a0_.x, a0_.y, a1_.x, a1_.y, a2_.x, a2_.y, a3_.x, a3_.y, a4_.x, a4_.y};
        float xaB[10] = {b0_.x, b0_.y, b1_.x, b1_.y, b2_.x, b2_.y, b3_.x, b3_.y, b4_.x, b4_.y};
        u64t bq0 = *(const u64t*)&swf[576], bq1 = *(const u64t*)&swf[578], bq2 = *(const u64t*)&swf[580];
        u64t bk0 = *(const u64t*)&swf[582], bk1 = *(const u64t*)&swf[584], bk2 = *(const u64t*)&swf[586];
        u64t bv0 = *(const u64t*)&swf[588], bv1 = *(const u64t*)&swf[590], bv2 = *(const u64t*)&swf[592];
        u64t qpA0 = bq0, qpA1 = bq1, qpA2 = bq2;
        u64t kpA0 = bk0, kpA1 = bk1, kpA2 = bk2;
        u64t vpA0 = bv0, vpA1 = bv1, vpA2 = bv2;
        u64t qpB0 = bq0, qpB1 = bq1, qpB2 = bq2;
        u64t kpB0 = bk0, kpB1 = bk1, kpB2 = bk2;
        u64t vpB0 = bv0, vpB1 = bv1, vpB2 = bv2;
#pragma unroll
        for (int kk = 0; kk < 10; kk++) {
            u64t xxA, xxB;
            F2PACK(xxA, xaA[kk], xaA[kk]);
            F2PACK(xxB, xaB[kk], xaB[kk]);
            ulonglong2 A = *(const ulonglong2*)&swf[kk * 8];
            u64t A2 = *(const u64t*)&swf[kk * 8 + 4];
            F2FMA(qpA0, xxA, A.x, qpA0); F2FMA(qpA1, xxA, A.y, qpA1); F2FMA(qpA2, xxA, A2, qpA2);
            F2FMA(qpB0, xxB, A.x, qpB0); F2FMA(qpB1, xxB, A.y, qpB1); F2FMA(qpB2, xxB, A2, qpB2);
            ulonglong2 B = *(const ulonglong2*)&swf[80 + kk * 8];
            u64t B2 = *(const u64t*)&swf[80 + kk * 8 + 4];
            F2FMA(kpA0, xxA, B.x, kpA0); F2FMA(kpA1, xxA, B.y, kpA1); F2FMA(kpA2, xxA, B2, kpA2);
            F2FMA(kpB0, xxB, B.x, kpB0); F2FMA(kpB1, xxB, B.y, kpB1); F2FMA(kpB2, xxB, B2, kpB2);
            ulonglong2 C = *(const ulonglong2*)&swf[160 + kk * 8];
            u64t C2 = *(const u64t*)&swf[160 + kk * 8 + 4];
            F2FMA(vpA0, xxA, C.x, vpA0); F2FMA(vpA1, xxA, C.y, vpA1); F2FMA(vpA2, xxA, C2, vpA2);
            F2FMA(vpB0, xxB, C.x, vpB0); F2FMA(vpB1, xxB, C.y, vpB1); F2FMA(vpB2, xxB, C2, vpB2);
        }
        {
            ulonglong2 m;
            m.x = kpA0; m.y = kpA1; sKV[w][0][lane][0] = m;
            m.x = kpA2; m.y = vpA0; sKV[w][0][lane][1] = m;
            m.x = vpA1; m.y = vpA2; sKV[w][0][lane][2] = m;
            m.x = kpB0; m.y = kpB1; sKV[w][1][lane][0] = m;
            m.x = kpB2; m.y = vpB0; sKV[w][1][lane][1] = m;
            m.x = vpB1; m.y = vpB2; sKV[w][1][lane][2] = m;
        }
        __syncwarp();
        float oA[6], oB[6];
        {
            u64t lpA, acA0, acA1, acA2, lpB, acB0, acB1, acB2;
            F2PACK(lpA, 0.f, 0.f);
            acA0 = lpA; acA1 = lpA; acA2 = lpA;
            lpB = lpA; acB0 = lpA; acB1 = lpA; acB2 = lpA;
#pragma unroll
            for (int tp = 0; tp < 32; tp++) {
                ulonglong2 ma0 = sKV[w][0][tp][0];
                ulonglong2 ma1 = sKV[w][0][tp][1];
                ulonglong2 ma2 = sKV[w][0][tp][2];
                ulonglong2 mb0 = sKV[w][1][tp][0];
                ulonglong2 mb1 = sKV[w][1][tp][1];
                ulonglong2 mb2 = sKV[w][1][tp][2];
                u64t tA, tB;
                F2MUL(tA, qpA2, ma1.x);
                F2FMA(tA, qpA1, ma0.y, tA);
                F2FMA(tA, qpA0, ma0.x, tA);
                F2MUL(tB, qpB2, mb1.x);
                F2FMA(tB, qpB1, mb0.y, tB);
                F2FMA(tB, qpB0, mb0.x, tB);
                float sA0, sA1, sB0, sB1;
                F2UNPACK(sA0, sA1, tA);
                F2UNPACK(sB0, sB1, tB);
                float eA0 = __expf(sA0), eA1 = __expf(sA1);
                float eB0 = __expf(sB0), eB1 = __expf(sB1);
                u64t epA, epB;
                F2PACK(epA, eA0, eA1);
                F2PACK(epB, eB0, eB1);
                F2ADD(lpA, lpA, epA);
                F2FMA(acA0, epA, ma1.y, acA0);
                F2FMA(acA1, epA, ma2.x, acA1);
                F2FMA(acA2, epA, ma2.y, acA2);
                F2ADD(lpB, lpB, epB);
                F2FMA(acB0, epB, mb1.y, acB0);
                F2FMA(acB1, epB, mb2.x, acB1);
                F2FMA(acB2, epB, mb2.y, acB2);
            }
            float l0, l1, x00, x10, x01, x11, x02, x12, q0, q3, q1, q4, q2, q5;
            F2UNPACK(l0, l1, lpA);
            F2UNPACK(x00, x10, acA0);
            F2UNPACK(x01, x11, acA1);
            F2UNPACK(x02, x12, acA2);
            F2UNPACK(q0, q3, qpA0);
            F2UNPACK(q1, q4, qpA1);
            F2UNPACK(q2, q5, qpA2);
            float i0 = 1.f / l0, i1 = 1.f / l1;
            oA[0] = q0 + x00 * i0; oA[1] = q1 + x01 * i0; oA[2] = q2 + x02 * i0;
            oA[3] = q3 + x10 * i1; oA[4] = q4 + x11 * i1; oA[5] = q5 + x12 * i1;
            F2UNPACK(l0, l1, lpB);
            F2UNPACK(x00, x10, acB0);
            F2UNPACK(x01, x11, acB1);
            F2UNPACK(x02, x12, acB2);
            F2UNPACK(q0, q3, qpB0);
            F2UNPACK(q1, q4, qpB1);
            F2UNPACK(q2, q5, qpB2);
            i0 = 1.f / l0; i1 = 1.f / l1;
            oB[0] = q0 + x00 * i0; oB[1] = q1 + x01 * i0; oB[2] = q2 + x02 * i0;
            oB[3] = q3 + x10 * i1; oB[4] = q4 + x11 * i1; oB[5] = q5 + x12 * i1;
        }
        __syncwarp();
        ln6r(oA, g0r, be0r);
        ln6r(oB, g0r, be0r);
        u64t hpA[12], hpB[12];
#pragma unroll
        for (int j = 0; j < 12; j++) {
            u64t t = *(const u64t*)&swf[606 + 2 * j];
            hpA[j] = t; hpB[j] = t;
        }
#pragma unroll
        for (int kk = 0; kk < 6; kk++) {
            u64t ooA, ooB;
            F2PACK(ooA, oA[kk], oA[kk]);
            F2PACK(ooB, oB[kk], oB[kk]);
            const ulonglong2* r = (const ulonglong2*)&swf[240 + kk * 24];
#pragma unroll
            for (int i = 0; i < 6; i++) {
                ulonglong2 rv = r[i];
                F2FMA(hpA[2 * i], ooA, rv.x, hpA[2 * i]);
                F2FMA(hpA[2 * i + 1], ooA, rv.y, hpA[2 * i + 1]);
                F2FMA(hpB[2 * i], ooB, rv.x, hpB[2 * i]);
                F2FMA(hpB[2 * i + 1], ooB, rv.y, hpB[2 * i + 1]);
            }
        }
        u64t fpA0 = *(const u64t*)&swf[630], fpA1 = *(const u64t*)&swf[632], fpA2 = *(const u64t*)&swf[634];
        u64t fpB0 = fpA0, fpB1 = fpA1, fpB2 = fpA2;
#pragma unroll
        for (int j = 0; j < 12; j++) {
            float la, ha, lb, hb;
            F2UNPACK(la, ha, hpA[j]);
            F2UNPACK(lb, hb, hpB[j]);
            la = fmaxf(la, 0.f); ha = fmaxf(ha, 0.f);
            lb = fmaxf(lb, 0.f); hb = fmaxf(hb, 0.f);
            u64t hAlo, hAhi, hBlo, hBhi;
            F2PACK(hAlo, la, la); F2PACK(hAhi, ha, ha);
            F2PACK(hBlo, lb, lb); F2PACK(hBhi, hb, hb);
            int jj = 2 * j;
            ulonglong2 rv0 = *(const ulonglong2*)&swf[384 + jj * 8];
            u64t rv0b = *(const u64t*)&swf[384 + jj * 8 + 4];
            ulonglong2 rv1 = *(const ulonglong2*)&swf[384 + (jj + 1) * 8];
            u64t rv1b = *(const u64t*)&swf[384 + (jj + 1) * 8 + 4];
            F2FMA(fpA0, hAlo, rv0.x, fpA0); F2FMA(fpA1, hAlo, rv0.y, fpA1); F2FMA(fpA2, hAlo, rv0b, fpA2);
            F2FMA(fpA0, hAhi, rv1.x, fpA0); F2FMA(fpA1, hAhi, rv1.y, fpA1); F2FMA(fpA2, hAhi, rv1b, fpA2);
            F2FMA(fpB0, hBlo, rv0.x, fpB0); F2FMA(fpB1, hBlo, rv0.y, fpB1); F2FMA(fpB2, hBlo, rv0b, fpB2);
            F2FMA(fpB0, hBhi, rv1.x, fpB0); F2FMA(fpB1, hBhi, rv1.y, fpB1); F2FMA(fpB2, hBhi, rv1b, fpB2);
        }
        {
            float f0, f3, f1, f4, f2, f5;
            F2UNPACK(f0, f3, fpA0);
            F2UNPACK(f1, f4, fpA1);
            F2UNPACK(f2, f5, fpA2);
            oA[0] += f0; oA[1] += f1; oA[2] += f2; oA[3] += f3; oA[4] += f4; oA[5] += f5;
            F2UNPACK(f0, f3, fpB0);
            F2UNPACK(f1, f4, fpB1);
            F2UNPACK(f2, f5, fpB2);
            oB[0] += f0; oB[1] += f1; oB[2] += f2; oB[3] += f3; oB[4] += f4; oB[5] += f5;
        }
        ln6r(oA, g1r, be1r);
        ln6r(oB, g1r, be1r);
#pragma unroll
        for (int j = 0; j < 6; j++) {
            float cA = oA[j] * wr;
            float cB = oB[j] * wr;
            cA += __shfl_xor_sync(0xffffffffu, cA, 16);
            cB += __shfl_xor_sync(0xffffffffu, cB, 16);
            cA += __shfl_xor_sync(0xffffffffu, cA, 8);
            cB += __shfl_xor_sync(0xffffffffu, cB, 8);
            cA += __shfl_xor_sync(0xffffffffu, cA, 4);
            cB += __shfl_xor_sync(0xffffffffu, cB, 4);
            cA += __shfl_xor_sync(0xffffffffu, cA, 2);
            cB += __shfl_xor_sync(0xffffffffu, cB, 2);
            cA += __shfl_xor_sync(0xffffffffu, cA, 1);
            cB += __shfl_xor_sync(0xffffffffu, cB, 1);
            if (lane == 0) {
                g_xt[(size_t)n0 * 6 + j] = cA + brepv;
                g_xt[(size_t)(n0 + 1) * 6 + j] = cB + brepv;
            }
        }
    }
}

// ---------------- Fused layer 2: GAT1 aggregation + GEMM2 + GAT2 scores ----------------
__global__ __launch_bounds__(256) void layer2_k(const float* __restrict__ b1,
                                                const float* __restrict__ W2,
                                                const float* __restrict__ att2) {
    __shared__ __align__(16) float sW[70 * 80];
    __shared__ float sAtt[160];
    __shared__ float sB1[64];
    __shared__ float srow[8][80];
    for (int i = threadIdx.x; i < 5600; i += 256) sW[i] = W2[i];
    if (threadIdx.x < 160) sAtt[threadIdx.x] = att2[threadIdx.x];
    if (threadIdx.x < 64) sB1[threadIdx.x] = b1[threadIdx.x];
    __syncthreads();
    int lane = threadIdx.x & 31;
    int w = threadIdx.x >> 5;
    int gw = (blockIdx.x * blockDim.x + threadIdx.x) >> 5;
    int nw = (gridDim.x * blockDim.x) >> 5;
    int hl = lane & 7;
    int eidx = lane >> 3;
    int c0 = lane * 2;
    int hh = lane >> 2;
    int cL = 2 * lane;
    int cH = 64 + 2 * lane;
    bool hiActive = lane < 8;
    float b1lo = sB1[c0], b1hi = sB1[c0 + 1];

    for (int d = gw; d < NN; d += nw) {
        int start = g_rowptr[d], deg = g_rowptr[d + 1] - start;
        float sdd = g_s1dst[d * 8 + hl];
        float fd1 = __expf(sdd), fd02 = __expf(0.2f * sdd);
        float2 ps = g_s1pack[d * 8 + hl];
        float eself;
        {
            float t = ps.y * ps.y;
            float es = t * t * ps.y;
            eself = (sdd + ps.x >= 0.f) ? fd1 * es : fd02 * ps.y;
        }
        float den = (eidx == 0) ? eself : 0.f;
        float wself = __shfl_sync(0xffffffffu, eself, hh);
        float2 xs = __half22float2(*(const __half2*)&g_xw1h[(size_t)d * 64 + c0]);
        float acc0 = wself * xs.x, acc1 = wself * xs.y;
        for (int base = 0; base < deg; base += 4) {
            int e = base + eidx;
            float wv = 0.f;
            int scol = 0;
            if (e < deg) {
                scol = g_col[start + e];
                float2 p = g_s1pack[scol * 8 + hl];
                float t = p.y * p.y;
                float es = t * t * p.y;
                wv = (sdd + p.x >= 0.f) ? fd1 * es : fd02 * p.y;
            }
            den += wv;
#pragma unroll
            for (int i = 0; i < 4; i++) {
                if (base + i < deg) {
                    int s = __shfl_sync(0xffffffffu, scol, i * 8);
                    float wgt = __shfl_sync(0xffffffffu, wv, i * 8 + hh);
                    float2 xv = __half22float2(*(const __half2*)&g_xw1h[(size_t)s * 64 + c0]);
                    acc0 += wgt * xv.x;
                    acc1 += wgt * xv.y;
                }
            }
        }
        den += __shfl_xor_sync(0xffffffffu, den, 8);
        den += __shfl_xor_sync(0xffffffffu, den, 16);
        float invden = 1.f / den;
        float inv = __shfl_sync(0xffffffffu, invden, hh);
        float v0 = acc0 * inv + b1lo, v1 = acc1 * inv + b1hi;
        v0 = v0 > 0.f ? v0 : (__expf(v0) - 1.f);
        v1 = v1 > 0.f ? v1 : (__expf(v1) - 1.f);
        float xtv = (lane < 6) ? g_xt[(size_t)d * 6 + lane] : 0.f;

        u64t a0p, a1p;
        F2PACK(a0p, 0.f, 0.f);
        a1p = a0p;
#pragma unroll
        for (int p = 0; p < 32; p++) {
            float xv0 = __shfl_sync(0xffffffffu, v0, p);
            float xv1 = __shfl_sync(0xffffffffu, v1, p);
            u64t xx0, xx1;
            F2PACK(xx0, xv0, xv0);
            F2PACK(xx1, xv1, xv1);
            u64t w0 = *(const u64t*)&sW[(2 * p) * 80 + cL];
            F2FMA(a0p, xx0, w0, a0p);
            u64t w1 = *(const u64t*)&sW[(2 * p + 1) * 80 + cL];
            F2FMA(a0p, xx1, w1, a0p);
            if (hiActive) {
                u64t wh0 = *(const u64t*)&sW[(2 * p) * 80 + cH];
                F2FMA(a1p, xx0, wh0, a1p);
                u64t wh1 = *(const u64t*)&sW[(2 * p + 1) * 80 + cH];
                F2FMA(a1p, xx1, wh1, a1p);
            }
        }
#pragma unroll
        for (int j = 0; j < 6; j++) {
            float xv = __shfl_sync(0xffffffffu, xtv, j);
            u64t xx; F2PACK(xx, xv, xv);
            u64t w0 = *(const u64t*)&sW[(64 + j) * 80 + cL];
            F2FMA(a0p, xx, w0, a0p);
            if (hiActive) {
                u64t wh = *(const u64t*)&sW[(64 + j) * 80 + cH];
                F2FMA(a1p, xx, wh, a1p);
            }
        }
        float aL0, aL1;
        F2UNPACK(aL0, aL1, a0p);
        *(__half2*)&g_xw2h[(size_t)d * 80 + cL] = __floats2half2_rn(aL0, aL1);
        srow[w][cL] = aL0;
        srow[w][cL + 1] = aL1;
        if (hiActive) {
            float aH0, aH1;
            F2UNPACK(aH0, aH1, a1p);
            *(__half2*)&g_xw2h[(size_t)d * 80 + cH] = __floats2half2_rn(aH0, aH1);
            srow[w][cH] = aH0;
            srow[w][cH + 1] = aH1;
        }
        __syncwarp();
        if (lane < 16) {
            int h = lane >> 1, part = lane & 1;
            const float* r = srow[w] + h * 10;
            const float* at = sAtt + h * 20 + part * 10;
            float s = 0.f;
#pragma unroll
            for (int c = 0; c < 10; c++) s += r[c] * at[c];
            if (part == 0) {
                g_s2dst[d * 8 + h] = s;
            } else {
                g_s2pack[d * 8 + h] = make_float2(s, __expf(0.2f * s));
            }
        }
        __syncwarp();
    }
}

// ---------------- GAT2 aggregation: factored exp (float2 pack) + fp16 rows ----------------
__global__ __launch_bounds__(256) void gat2_agg_k(const float* __restrict__ b2,
                                                  float* __restrict__ out) {
    __shared__ float sacc[8][80];
    __shared__ float sval[8][16];
    int gw = (blockIdx.x * blockDim.x + threadIdx.x) >> 5;
    if (gw >= NN) return;
    int lane = threadIdx.x & 31;
    int w = (threadIdx.x >> 5);
    int d = gw;
    int start = g_rowptr[d], deg = g_rowptr[d + 1] - start;
    int hl = lane & 7;
    int eidx = lane >> 3;
    float sdd = g_s2dst[d * 8 + hl];
    float fd1 = __expf(sdd), fd02 = __expf(0.2f * sdd);
    float2 ps = g_s2pack[d * 8 + hl];
    float eself;
    {
        float t = ps.y * ps.y;
        float es = t * t * ps.y;
        eself = (sdd + ps.x >= 0.f) ? fd1 * es : fd02 * ps.y;
    }
    float den = (eidx == 0) ? eself : 0.f;
    int h0 = lane / 10;
    int h1 = (lane + 32) / 10;
    int h2 = (lane + 64) / 10;
    int i2 = 64 + (lane & 15);
    float ws0 = __shfl_sync(0xffffffffu, eself, h0);
    float ws1 = __shfl_sync(0xffffffffu, eself, h1);
    float ws2 = __shfl_sync(0xffffffffu, eself, h2);
    const __half* xd = &g_xw2h[(size_t)d * 80];
    float acc0 = ws0 * __half2float(xd[lane]);
    float acc1 = ws1 * __half2float(xd[32 + lane]);
    float acc2 = ws2 * __half2float(xd[i2]);
    for (int base = 0; base < deg; base += 4) {
        int e = base + eidx;
        float wv = 0.f;
        int scol = 0;
        if (e < deg) {
            scol = g_col[start + e];
            float2 p = g_s2pack[scol * 8 + hl];
            float t = p.y * p.y;
            float es = t * t * p.y;
            wv = (sdd + p.x >= 0.f) ? fd1 * es : fd02 * p.y;
        }
        den += wv;
#pragma unroll
        for (int i = 0; i < 4; i++) {
            if (base + i < deg) {
                int s = __shfl_sync(0xffffffffu, scol, i * 8);
                float w0 = __shfl_sync(0xffffffffu, wv, i * 8 + h0);
                float w1 = __shfl_sync(0xffffffffu, wv, i * 8 + h1);
                float w2 = __shfl_sync(0xffffffffu, wv, i * 8 + h2);
                const __half* xr = &g_xw2h[(size_t)s * 80];
                acc0 += w0 * __half2float(xr[lane]);
                acc1 += w1 * __half2float(xr[32 + lane]);
                acc2 += w2 * __half2float(xr[i2]);
            }
        }
    }
    den += __shfl_xor_sync(0xffffffffu, den, 8);
    den += __shfl_xor_sync(0xffffffffu, den, 16);
    float invden = 1.f / den;
    float iv0 = __shfl_sync(0xffffffffu, invden, h0);
    float iv1 = __shfl_sync(0xffffffffu, invden, h1);
    float iv2 = __shfl_sync(0xffffffffu, invden, h2);
    sacc[w][lane] = acc0 * iv0;
    sacc[w][32 + lane] = acc1 * iv1;
    if (lane < 16) sacc[w][i2] = acc2 * iv2;
    __syncwarp();
    if (lane < 10) {
        float s = 0.f;
#pragma unroll
        for (int h = 0; h < 8; h++) s += sacc[w][h * 10 + lane];
        sval[w][lane] = s * 0.125f + b2[lane];
    }
    __syncwarp();
    if (lane < 10) {
        float mx = -INFINITY;
#pragma unroll
        for (int c = 0; c < 10; c++) mx = fmaxf(mx, sval[w][c]);
        float se = 0.f;
#pragma unroll
        for (int c = 0; c < 10; c++) se += __expf(sval[w][c] - mx);
        out[(size_t)d * 10 + lane] = sval[w][lane] - mx - logf(se);
    }
}

// ---------------- launch ----------------
extern "C" void kernel_launch(void* const* d_in, const int* in_sizes, int n_in,
                              void* d_out, int out_size) {
    const float* x    = (const float*)d_in[0];
    const int*   ei   = (const int*)d_in[1];
    const float* ef   = (const float*)d_in[2];
    const float* W1   = (const float*)d_in[3];
    const float* att1 = (const float*)d_in[4];
    const float* b1   = (const float*)d_in[5];
    const float* W2   = (const float*)d_in[6];
    const float* att2 = (const float*)d_in[7];
    const float* b2   = (const float*)d_in[8];
    const float* Wq   = (const float*)d_in[9];
    const float* bq   = (const float*)d_in[10];
    const float* Wk   = (const float*)d_in[11];
    const float* bk   = (const float*)d_in[12];
    const float* Wv   = (const float*)d_in[13];
    const float* bv   = (const float*)d_in[14];
    const float* g0   = (const float*)d_in[15];
    const float* be0  = (const float*)d_in[16];
    const float* Wf1  = (const float*)d_in[17];
    const float* bf1  = (const float*)d_in[18];
    const float* Wf2  = (const float*)d_in[19];
    const float* bf2  = (const float*)d_in[20];
    const float* g1   = (const float*)d_in[21];
    const float* be1  = (const float*)d_in[22];
    const float* Wrep = (const float*)d_in[23];
    const float* brep = (const float*)d_in[24];
    float* out = (float*)d_out;
    int E = in_sizes[1] / 2;

    static cudaStream_t sB = 0, sC = 0;
    static cudaEvent_t evFork = 0, evB = 0, evC = 0;
    if (sB == 0) {
        cudaStreamCreateWithFlags(&sB, cudaStreamNonBlocking);
        cudaStreamCreateWithFlags(&sC, cudaStreamNonBlocking);
        cudaEventCreateWithFlags(&evFork, cudaEventDisableTiming);
        cudaEventCreateWithFlags(&evB, cudaEventDisableTiming);
        cudaEventCreateWithFlags(&evC, cudaEventDisableTiming);
    }

    cudaEventRecord(evFork, 0);
    cudaStreamWaitEvent(sB, evFork, 0);
    cudaStreamWaitEvent(sC, evFork, 0);

    gemm1_k<<<1184, 256, 0, sB>>>(x, W1, att1);
    cudaEventRecord(evB, sB);

    encoder_k<<<1184, 256, 0, sC>>>(ef, Wq, bq, Wk, bk, Wv, bv, g0, be0,
                                    Wf1, bf1, Wf2, bf2, g1, be1, Wrep, brep);
    cudaEventRecord(evC, sC);

    zero_deg_k<<<(NN + 255) / 256, 256>>>();
    hist_k<<<(E + 255) / 256, 256>>>(ei, E);
    scan1_k<<<(NN + 1023) / 1024, 256>>>();
    scan2_k<<<1, 128>>>((NN + 1023) / 1024);
    scan3_k<<<(NN + 1023) / 1024, 256>>>();
    fill_k<<<(E + 255) / 256, 256>>>(ei, E);

    cudaStreamWaitEvent(0, evB, 0);
    cudaStreamWaitEvent(0, evC, 0);
    layer2_k<<<1184, 256>>>(b1, W2, att2);
    gat2_agg_k<<<(NN + 7) / 8, 256>>>(b2, out);
}